// round 10
// baseline (speedup 1.0000x reference)
#include <cuda_runtime.h>
#include <cuda_fp16.h>

// Shapes (fixed by the problem)
#define BB   4
#define CC   128
#define NPTS 8192
#define KNN  16
#define OO   128
#define CNT1 32768.0f                // B*N      (stats count for central channels)
#define CNT2 524288.0f               // B*N*K    (stats count for diff channels)

// Scratch (static device globals — allocation-free per harness rules)
__device__ float    g_localT[BB*NPTS*OO];   // (B,N,O) fp32, 16 MB
__device__ unsigned g_edgeH [BB*NPTS*64];   // (B,N,O/2) half2-packed, 8 MB
__device__ float    g_acc[512];             // sum_l | sq_l | sum_d | sq_d

// ---------------------------------------------------------------------------
// helpers: bit casts, tf32 convert, mma.sync m16n8k8
// ---------------------------------------------------------------------------
__device__ __forceinline__ unsigned h2u(__half2 h) {
    return *reinterpret_cast<unsigned*>(&h);
}
__device__ __forceinline__ float2 u2f2(unsigned u) {
    return __half22float2(*reinterpret_cast<__half2*>(&u));
}

__device__ __forceinline__ unsigned f2tf32(float x) {
    unsigned y;
    asm("cvt.rna.tf32.f32 %0, %1;" : "=r"(y) : "f"(x));
    return y;
}

__device__ __forceinline__ void mma_tf32(float c[4], const unsigned a[4], const unsigned b[2]) {
    asm("mma.sync.aligned.m16n8k8.row.col.f32.tf32.tf32.f32 "
        "{%0,%1,%2,%3}, {%4,%5,%6,%7}, {%8,%9}, {%0,%1,%2,%3};"
        : "+f"(c[0]), "+f"(c[1]), "+f"(c[2]), "+f"(c[3])
        : "r"(a[0]), "r"(a[1]), "r"(a[2]), "r"(a[3]),
          "r"(b[0]), "r"(b[1]));
}

// ---------------------------------------------------------------------------
// K1: dual GEMM via tf32 tensor cores, fragment-packed smem staging.
//   C[m][n] = sum_c W[m][c] * feat[b][c][n0+n]
// Block: 128 channels (mb -> W1/W2) x 128 points; K=128 in 32-chunks.
// 8 warps: 2(m) x 4(n), warp tile 64x32, mma m16n8k8.
// smem layouts (per 32-k chunk):
//   A: 16 rows (ks*4+tig), each 66 float4; float4 = {a0,a1,a2,a3} fragment
//   B: 16 rows (ks*4+tig), each 132 float2; float2 = {b0,b1} fragment
// localT stored fp32; edge stored half2-packed.
// ---------------------------------------------------------------------------
__global__ void __launch_bounds__(256, 2) k_gemm(const float* __restrict__ feat,
                                                 const float* __restrict__ W1,
                                                 const float* __restrict__ W2) {
    __shared__ float smem_s[8448];             // A: [0,4224) floats, B: [4224,8448)
    float* As = smem_s;                        // viewed as 1056 float4
    float* Bs = smem_s + 4224;                 // viewed as 2112 float2

    const int tid = threadIdx.x;
    if (blockIdx.x == 0) {                     // re-zero stat accumulators every replay
        for (int t = tid; t < 512; t += 256) g_acc[t] = 0.f;
    }
    const int mb = blockIdx.x >> 8;            // 0: W1 -> localT, 1: W2 -> edgeH
    const int b  = (blockIdx.x >> 6) & 3;
    const int n0 = (blockIdx.x & 63) << 7;

    const float* Wsel = mb ? W2 : W1;
    const float* fb   = feat + b * (CC * NPTS) + n0;

    const int wid  = tid >> 5, lane = tid & 31;
    const int wm   = (wid >> 2) << 6;          // warp m base: 0 or 64
    const int wn   = (wid & 3) << 5;           // warp n base: 0..96
    const int g    = lane >> 2;                // 0..7
    const int tig  = lane & 3;                 // 0..3

    float acc[4][4][4];
#pragma unroll
    for (int mt = 0; mt < 4; ++mt)
#pragma unroll
        for (int nt = 0; nt < 4; ++nt)
#pragma unroll
            for (int q = 0; q < 4; ++q) acc[mt][nt][q] = 0.f;

    for (int kc = 0; kc < 128; kc += 32) {
        __syncthreads();
        // ---- stage A: W rows -> fragment-order float4s (scalar scatter) ----
#pragma unroll
        for (int t = 0; t < 4; ++t) {
            const int i  = tid + (t << 8);     // 0..1023
            const int m  = i >> 3;             // 0..127
            const int jj = i & 7;              // k/4 within chunk
            const float4 v = *(const float4*)(Wsel + m * 128 + kc + (jj << 2));
            const int ks   = jj >> 1;
            const int comp = ((m >> 3) & 1) + ((jj & 1) << 1);
            const int base = ((m >> 4) << 3) + (m & 7);   // mb16*8 + g
            const float va[4] = {v.x, v.y, v.z, v.w};
#pragma unroll
            for (int c = 0; c < 4; ++c)
                As[((ks * 4 + c) * 66 + base) * 4 + comp] = __uint_as_float(f2tf32(va[c]));
        }
        // ---- stage B: paired k/k+4 loads -> fragment float2s (float4 STS) ----
#pragma unroll
        for (int t = 0; t < 4; ++t) {
            const int i  = tid + (t << 8);     // 0..1023
            const int r  = i >> 6;             // row id = ks*4+tig, 0..15
            const int n  = (i & 63) << 1;      // 0..126, even
            const int kl = ((r >> 2) << 3) + (r & 3);
            const float2 lo = *(const float2*)(fb + (kc + kl)     * NPTS + n);
            const float2 hi = *(const float2*)(fb + (kc + kl + 4) * NPTS + n);
            float4 o;
            o.x = __uint_as_float(f2tf32(lo.x));
            o.y = __uint_as_float(f2tf32(hi.x));
            o.z = __uint_as_float(f2tf32(lo.y));
            o.w = __uint_as_float(f2tf32(hi.y));
            *(float4*)&Bs[(r * 132 + n) * 2] = o;
        }
        __syncthreads();

        // ---- 4 k-steps of 8 ----
#pragma unroll
        for (int ks = 0; ks < 4; ++ks) {
            const float4* Arow = (const float4*)As + (ks * 4 + tig) * 66 + ((wm >> 4) << 3) + g;
            const float2* Brow = (const float2*)Bs + (ks * 4 + tig) * 132 + wn + g;

            unsigned afr[4][4], bfr[4][2];
#pragma unroll
            for (int mt = 0; mt < 4; ++mt) {
                const float4 a = Arow[mt << 3];
                afr[mt][0] = __float_as_uint(a.x);
                afr[mt][1] = __float_as_uint(a.y);
                afr[mt][2] = __float_as_uint(a.z);
                afr[mt][3] = __float_as_uint(a.w);
            }
#pragma unroll
            for (int nt = 0; nt < 4; ++nt) {
                const float2 bv = Brow[nt << 3];
                bfr[nt][0] = __float_as_uint(bv.x);
                bfr[nt][1] = __float_as_uint(bv.y);
            }
#pragma unroll
            for (int mt = 0; mt < 4; ++mt)
#pragma unroll
                for (int nt = 0; nt < 4; ++nt)
                    mma_tf32(acc[mt][nt], afr[mt], bfr[nt]);
        }
    }

    // ---- epilogue: per-warp transpose via smem (reuse staging region) ----
    __syncthreads();                            // all warps done reading As/Bs
    float* wb = smem_s + wid * 544;             // per-warp [8][68]

#pragma unroll
    for (int nt = 0; nt < 4; ++nt) {
        __syncwarp();
#pragma unroll
        for (int mt = 0; mt < 4; ++mt) {
            float* wr0 = wb + (2 * tig) * 68 + (mt << 4) + g;
            float* wr1 = wb + (2 * tig + 1) * 68 + (mt << 4) + g;
            wr0[0] = acc[mt][nt][0];
            wr1[0] = acc[mt][nt][1];
            wr0[8] = acc[mt][nt][2];
            wr1[8] = acc[mt][nt][3];
        }
        __syncwarp();
#pragma unroll
        for (int r = 0; r < 4; ++r) {
            const int j  = lane + (r << 5);     // 0..127
            const int nl = j >> 4;              // 0..7 (local n)
            const int mq = (j & 15) << 2;       // 0..60 (m offset)
            const float4 v = *(const float4*)&wb[nl * 68 + mq];
            const int n = n0 + wn + (nt << 3) + nl;
            const int p = b * NPTS + n;
            if (mb == 0) {
                *(float4*)&g_localT[((size_t)p << 7) + wm + mq] = v;
            } else {
                uint2 h;
                h.x = h2u(__floats2half2_rn(v.x, v.y));
                h.y = h2u(__floats2half2_rn(v.z, v.w));
                *(uint2*)&g_edgeH[((size_t)p << 6) + ((wm + mq) >> 1)] = h;
            }
        }
    }
}

// ---------------------------------------------------------------------------
// K2: BN statistics. Warp per point (64 points/block, grid 512).
// Lane owns 4 channels. Edge gathered as half2 pairs (8B/lane/neighbor).
// ---------------------------------------------------------------------------
__global__ void __launch_bounds__(256) k_stats(const int* __restrict__ knn) {
    const int tid = threadIdx.x, lane = tid & 31, warp = tid >> 5;

    float sl[4]  = {0.f, 0.f, 0.f, 0.f};
    float sql[4] = {0.f, 0.f, 0.f, 0.f};
    float sd[4]  = {0.f, 0.f, 0.f, 0.f};
    float sqd[4] = {0.f, 0.f, 0.f, 0.f};

    const int pbase = blockIdx.x * 64 + warp * 8;
    const int c0 = lane << 2;

    for (int iter = 0; iter < 8; ++iter) {
        const int p = pbase + iter;               // p = b*8192 + n
        const int b = p >> 13;
        int myidx = 0;
        if (lane < 16) myidx = knn[p * 16 + lane];

        const float4 lv = *(const float4*)&g_localT[((size_t)p << 7) + c0];
        sl[0] += lv.x; sql[0] += lv.x * lv.x;
        sl[1] += lv.y; sql[1] += lv.y * lv.y;
        sl[2] += lv.z; sql[2] += lv.z * lv.z;
        sl[3] += lv.w; sql[3] += lv.w * lv.w;

        const unsigned* ebh = g_edgeH + ((size_t)b << 19);
#pragma unroll
        for (int k = 0; k < 16; ++k) {
            const int ik = __shfl_sync(0xffffffffu, myidx, k);
            const uint2 ev = *(const uint2*)&ebh[((size_t)ik << 6) + (lane << 1)];
            const float2 e01 = u2f2(ev.x);
            const float2 e23 = u2f2(ev.y);
            float d0 = e01.x - lv.x; sd[0] += d0; sqd[0] += d0 * d0;
            float d1 = e01.y - lv.y; sd[1] += d1; sqd[1] += d1 * d1;
            float d2 = e23.x - lv.z; sd[2] += d2; sqd[2] += d2 * d2;
            float d3 = e23.y - lv.w; sd[3] += d3; sqd[3] += d3 * d3;
        }
    }

    __shared__ float sacc[512];
    for (int t = tid; t < 512; t += 256) sacc[t] = 0.f;
    __syncthreads();
#pragma unroll
    for (int j = 0; j < 4; ++j) {
        atomicAdd(&sacc[c0 + j],        sl[j]);
        atomicAdd(&sacc[128 + c0 + j],  sql[j]);
        atomicAdd(&sacc[256 + c0 + j],  sd[j]);
        atomicAdd(&sacc[384 + c0 + j],  sqd[j]);
    }
    __syncthreads();
    for (int t = tid; t < 512; t += 256) atomicAdd(&g_acc[t], sacc[t]);
}

// ---------------------------------------------------------------------------
// K3: output. Block = (batch b, 32-wide n tile). Warp per point; BN params
// derived per block from g_acc. Transposed through padded smem for coalesced
// (B,256,N) stores.
// ---------------------------------------------------------------------------
__global__ void __launch_bounds__(256) k_out(const int* __restrict__ knn,
                                             const float* __restrict__ gamma,
                                             const float* __restrict__ beta,
                                             float* __restrict__ out) {
    __shared__ float s_a[256], s_sh[256];
    __shared__ float s_o1[128 * 33];
    __shared__ float s_o2[128 * 33];

    const int tid = threadIdx.x;
    {   // derive BN affine params (256 threads, one channel each)
        const int ch = tid;
        float s, sq, inv_cnt;
        if (ch < 128) { s = g_acc[ch];       sq = g_acc[128 + ch]; inv_cnt = 1.f / CNT1; }
        else          { s = g_acc[128 + ch]; sq = g_acc[256 + ch]; inv_cnt = 1.f / CNT2; }
        const float mean = s * inv_cnt;
        const float var  = fmaxf(sq * inv_cnt - mean * mean, 0.f);
        const float a    = gamma[ch] * rsqrtf(var + 1e-5f);
        s_a[ch]  = a;
        s_sh[ch] = beta[ch] - a * mean;
    }
    __syncthreads();

    const int b  = blockIdx.x >> 8;
    const int n0 = (blockIdx.x & 255) << 5;
    const int lane = tid & 31, warp = tid >> 5;
    const int c0 = lane << 2;

    float a1[4], sh1[4], a2[4], sh2[4];
#pragma unroll
    for (int j = 0; j < 4; ++j) {
        a1[j]  = s_a[c0 + j];        sh1[j] = s_sh[c0 + j];
        a2[j]  = s_a[128 + c0 + j];  sh2[j] = s_sh[128 + c0 + j];
    }

    const unsigned* ebh = g_edgeH + ((size_t)b << 19);
    for (int iter = 0; iter < 4; ++iter) {
        const int i = warp * 4 + iter;           // 0..31
        const int p = (b << 13) + n0 + i;
        int myidx = 0;
        if (lane < 16) myidx = knn[p * 16 + lane];

        const float4 lv = *(const float4*)&g_localT[((size_t)p << 7) + c0];
        const float l[4] = {lv.x, lv.y, lv.z, lv.w};
        float accf[4] = {0.f, 0.f, 0.f, 0.f};
#pragma unroll
        for (int k = 0; k < 16; ++k) {
            const int ik = __shfl_sync(0xffffffffu, myidx, k);
            const uint2 ev = *(const uint2*)&ebh[((size_t)ik << 6) + (lane << 1)];
            const float2 e01 = u2f2(ev.x);
            const float2 e23 = u2f2(ev.y);
            const float e[4] = {e01.x, e01.y, e23.x, e23.y};
#pragma unroll
            for (int j = 0; j < 4; ++j)
                accf[j] += fmaxf(a2[j] * (e[j] - l[j]) + sh2[j], 0.f);
        }
#pragma unroll
        for (int j = 0; j < 4; ++j) {
            s_o1[(c0 + j) * 33 + i] = fmaxf(a1[j] * l[j] + sh1[j], 0.f);
            s_o2[(c0 + j) * 33 + i] = accf[j] * (1.f / 16.f);
        }
    }
    __syncthreads();

    float* ob = out + ((size_t)b << 21) + n0;    // b*256*8192
#pragma unroll
    for (int r = 0; r < 16; ++r) {
        const int t  = tid + (r << 8);
        const int c  = t >> 5;
        const int i2 = t & 31;
        ob[(size_t)c * NPTS + i2]         = s_o1[c * 33 + i2];
        ob[(size_t)(c + 128) * NPTS + i2] = s_o2[c * 33 + i2];
    }
}

// ---------------------------------------------------------------------------
extern "C" void kernel_launch(void* const* d_in, const int* in_sizes, int n_in,
                              void* d_out, int out_size) {
    const float* feat  = (const float*)d_in[0];
    const int*   knn   = (const int*)  d_in[1];
    const float* W1    = (const float*)d_in[2];
    const float* W2    = (const float*)d_in[3];
    const float* gamma = (const float*)d_in[4];
    const float* beta  = (const float*)d_in[5];
    float* out = (float*)d_out;

    k_gemm <<<512, 256>>>(feat, W1, W2);
    k_stats<<<512, 256>>>(knn);
    k_out  <<<1024, 256>>>(knn, gamma, beta, out);
}

// round 11
// speedup vs baseline: 1.0489x; 1.0489x over previous
#include <cuda_runtime.h>
#include <cuda_fp16.h>

// Shapes (fixed by the problem)
#define BB   4
#define CC   128
#define NPTS 8192
#define KNN  16
#define OO   128
#define CNT1 32768.0f                // B*N      (stats count for central channels)
#define CNT2 524288.0f               // B*N*K    (stats count for diff channels)

// Scratch (static device globals — allocation-free per harness rules)
__device__ float    g_localT[BB*NPTS*OO];   // (B,N,O) fp32, 16 MB
__device__ unsigned g_edgeH [BB*NPTS*64];   // (B,N,O/2) half2-packed, 8 MB
__device__ float    g_acc[512];             // sum_l | sq_l | sum_d | sq_d

// ---------------------------------------------------------------------------
// helpers: bit casts, tf32 convert, mma.sync m16n8k8
// ---------------------------------------------------------------------------
__device__ __forceinline__ unsigned h2u(__half2 h) {
    return *reinterpret_cast<unsigned*>(&h);
}
__device__ __forceinline__ float2 u2f2(unsigned u) {
    return __half22float2(*reinterpret_cast<__half2*>(&u));
}

__device__ __forceinline__ unsigned f2tf32(float x) {
    unsigned y;
    asm("cvt.rna.tf32.f32 %0, %1;" : "=r"(y) : "f"(x));
    return y;
}

__device__ __forceinline__ void mma_tf32(float c[4], const unsigned a[4], const unsigned b[2]) {
    asm("mma.sync.aligned.m16n8k8.row.col.f32.tf32.tf32.f32 "
        "{%0,%1,%2,%3}, {%4,%5,%6,%7}, {%8,%9}, {%0,%1,%2,%3};"
        : "+f"(c[0]), "+f"(c[1]), "+f"(c[2]), "+f"(c[3])
        : "r"(a[0]), "r"(a[1]), "r"(a[2]), "r"(a[3]),
          "r"(b[0]), "r"(b[1]));
}

// ---------------------------------------------------------------------------
// K1: dual GEMM via tf32 tensor cores, fragment-packed smem staging.
// (unchanged from R10 — 24.4us, tensor 28.7%)
// ---------------------------------------------------------------------------
__global__ void __launch_bounds__(256, 2) k_gemm(const float* __restrict__ feat,
                                                 const float* __restrict__ W1,
                                                 const float* __restrict__ W2) {
    __shared__ float smem_s[8448];             // A: [0,4224) floats, B: [4224,8448)
    float* As = smem_s;                        // viewed as 1056 float4
    float* Bs = smem_s + 4224;                 // viewed as 2112 float2

    const int tid = threadIdx.x;
    if (blockIdx.x == 0) {                     // re-zero stat accumulators every replay
        for (int t = tid; t < 512; t += 256) g_acc[t] = 0.f;
    }
    const int mb = blockIdx.x >> 8;            // 0: W1 -> localT, 1: W2 -> edgeH
    const int b  = (blockIdx.x >> 6) & 3;
    const int n0 = (blockIdx.x & 63) << 7;

    const float* Wsel = mb ? W2 : W1;
    const float* fb   = feat + b * (CC * NPTS) + n0;

    const int wid  = tid >> 5, lane = tid & 31;
    const int wm   = (wid >> 2) << 6;          // warp m base: 0 or 64
    const int wn   = (wid & 3) << 5;           // warp n base: 0..96
    const int g    = lane >> 2;                // 0..7
    const int tig  = lane & 3;                 // 0..3

    float acc[4][4][4];
#pragma unroll
    for (int mt = 0; mt < 4; ++mt)
#pragma unroll
        for (int nt = 0; nt < 4; ++nt)
#pragma unroll
            for (int q = 0; q < 4; ++q) acc[mt][nt][q] = 0.f;

    for (int kc = 0; kc < 128; kc += 32) {
        __syncthreads();
        // ---- stage A: W rows -> fragment-order float4s (scalar scatter) ----
#pragma unroll
        for (int t = 0; t < 4; ++t) {
            const int i  = tid + (t << 8);     // 0..1023
            const int m  = i >> 3;             // 0..127
            const int jj = i & 7;              // k/4 within chunk
            const float4 v = *(const float4*)(Wsel + m * 128 + kc + (jj << 2));
            const int ks   = jj >> 1;
            const int comp = ((m >> 3) & 1) + ((jj & 1) << 1);
            const int base = ((m >> 4) << 3) + (m & 7);   // mb16*8 + g
            const float va[4] = {v.x, v.y, v.z, v.w};
#pragma unroll
            for (int c = 0; c < 4; ++c)
                As[((ks * 4 + c) * 66 + base) * 4 + comp] = __uint_as_float(f2tf32(va[c]));
        }
        // ---- stage B: paired k/k+4 loads -> fragment float2s (float4 STS) ----
#pragma unroll
        for (int t = 0; t < 4; ++t) {
            const int i  = tid + (t << 8);     // 0..1023
            const int r  = i >> 6;             // row id = ks*4+tig, 0..15
            const int n  = (i & 63) << 1;      // 0..126, even
            const int kl = ((r >> 2) << 3) + (r & 3);
            const float2 lo = *(const float2*)(fb + (kc + kl)     * NPTS + n);
            const float2 hi = *(const float2*)(fb + (kc + kl + 4) * NPTS + n);
            float4 o;
            o.x = __uint_as_float(f2tf32(lo.x));
            o.y = __uint_as_float(f2tf32(hi.x));
            o.z = __uint_as_float(f2tf32(lo.y));
            o.w = __uint_as_float(f2tf32(hi.y));
            *(float4*)&Bs[(r * 132 + n) * 2] = o;
        }
        __syncthreads();

        // ---- 4 k-steps of 8 ----
#pragma unroll
        for (int ks = 0; ks < 4; ++ks) {
            const float4* Arow = (const float4*)As + (ks * 4 + tig) * 66 + ((wm >> 4) << 3) + g;
            const float2* Brow = (const float2*)Bs + (ks * 4 + tig) * 132 + wn + g;

            unsigned afr[4][4], bfr[4][2];
#pragma unroll
            for (int mt = 0; mt < 4; ++mt) {
                const float4 a = Arow[mt << 3];
                afr[mt][0] = __float_as_uint(a.x);
                afr[mt][1] = __float_as_uint(a.y);
                afr[mt][2] = __float_as_uint(a.z);
                afr[mt][3] = __float_as_uint(a.w);
            }
#pragma unroll
            for (int nt = 0; nt < 4; ++nt) {
                const float2 bv = Brow[nt << 3];
                bfr[nt][0] = __float_as_uint(bv.x);
                bfr[nt][1] = __float_as_uint(bv.y);
            }
#pragma unroll
            for (int mt = 0; mt < 4; ++mt)
#pragma unroll
                for (int nt = 0; nt < 4; ++nt)
                    mma_tf32(acc[mt][nt], afr[mt], bfr[nt]);
        }
    }

    // ---- epilogue: per-warp transpose via smem (reuse staging region) ----
    __syncthreads();                            // all warps done reading As/Bs
    float* wb = smem_s + wid * 544;             // per-warp [8][68]

#pragma unroll
    for (int nt = 0; nt < 4; ++nt) {
        __syncwarp();
#pragma unroll
        for (int mt = 0; mt < 4; ++mt) {
            float* wr0 = wb + (2 * tig) * 68 + (mt << 4) + g;
            float* wr1 = wb + (2 * tig + 1) * 68 + (mt << 4) + g;
            wr0[0] = acc[mt][nt][0];
            wr1[0] = acc[mt][nt][1];
            wr0[8] = acc[mt][nt][2];
            wr1[8] = acc[mt][nt][3];
        }
        __syncwarp();
#pragma unroll
        for (int r = 0; r < 4; ++r) {
            const int j  = lane + (r << 5);     // 0..127
            const int nl = j >> 4;              // 0..7 (local n)
            const int mq = (j & 15) << 2;       // 0..60 (m offset)
            const float4 v = *(const float4*)&wb[nl * 68 + mq];
            const int n = n0 + wn + (nt << 3) + nl;
            const int p = b * NPTS + n;
            if (mb == 0) {
                *(float4*)&g_localT[((size_t)p << 7) + wm + mq] = v;
            } else {
                uint2 h;
                h.x = h2u(__floats2half2_rn(v.x, v.y));
                h.y = h2u(__floats2half2_rn(v.z, v.w));
                *(uint2*)&g_edgeH[((size_t)p << 6) + ((wm + mq) >> 1)] = h;
            }
        }
    }
}

// ---------------------------------------------------------------------------
// K2: BN statistics. Warp processes TWO points concurrently:
//   h = lane>>4 selects point within pair, q = lane&15 owns 8 channels (uint4).
// One warp LDG.128 fetches two full 256B neighbor rows -> half the memory
// instructions, doubled bytes-in-flight vs R10.
// ---------------------------------------------------------------------------
__global__ void __launch_bounds__(256) k_stats(const int* __restrict__ knn) {
    const int tid = threadIdx.x, lane = tid & 31, warp = tid >> 5;
    const int h = lane >> 4;                   // 0/1: point within pair
    const int q = lane & 15;                   // 8-channel slot
    const int c0 = q << 3;

    const int pbase = blockIdx.x * 64 + warp * 8;     // 64 | 8192 -> same batch
    const int b = pbase >> 13;
    const unsigned* ebh = g_edgeH + ((size_t)b << 19);

    float sl[8], sql[8], sd[8], sqd[8];
#pragma unroll
    for (int j = 0; j < 8; ++j) { sl[j] = sql[j] = sd[j] = sqd[j] = 0.f; }

#pragma unroll
    for (int it = 0; it < 4; ++it) {
        const int p  = pbase + (it << 1) + h;
        const int iv = knn[p * 16 + q];        // all 32 lanes valid (q<16)

        const float4 l0 = *(const float4*)&g_localT[((size_t)p << 7) + c0];
        const float4 l1 = *(const float4*)&g_localT[((size_t)p << 7) + c0 + 4];
        const float l[8] = {l0.x, l0.y, l0.z, l0.w, l1.x, l1.y, l1.z, l1.w};
#pragma unroll
        for (int j = 0; j < 8; ++j) { sl[j] += l[j]; sql[j] += l[j] * l[j]; }

#pragma unroll
        for (int k = 0; k < 16; ++k) {
            const int ik = __shfl_sync(0xffffffffu, iv, (h << 4) + k);
            const uint4 ev = *(const uint4*)&ebh[((size_t)ik << 6) + (q << 2)];
            const float2 e01 = u2f2(ev.x);
            const float2 e23 = u2f2(ev.y);
            const float2 e45 = u2f2(ev.z);
            const float2 e67 = u2f2(ev.w);
            const float e[8] = {e01.x, e01.y, e23.x, e23.y, e45.x, e45.y, e67.x, e67.y};
#pragma unroll
            for (int j = 0; j < 8; ++j) {
                const float d = e[j] - l[j];
                sd[j] += d; sqd[j] += d * d;
            }
        }
    }

    __shared__ float sacc[512];
    for (int t = tid; t < 512; t += 256) sacc[t] = 0.f;
    __syncthreads();
#pragma unroll
    for (int j = 0; j < 8; ++j) {
        atomicAdd(&sacc[c0 + j],        sl[j]);
        atomicAdd(&sacc[128 + c0 + j],  sql[j]);
        atomicAdd(&sacc[256 + c0 + j],  sd[j]);
        atomicAdd(&sacc[384 + c0 + j],  sqd[j]);
    }
    __syncthreads();
    for (int t = tid; t < 512; t += 256) atomicAdd(&g_acc[t], sacc[t]);
}

// ---------------------------------------------------------------------------
// K3: output. Same paired-point / 8-channel-per-lane gather as K2. BN params
// derived per block from g_acc. Transposed through padded smem for coalesced
// (B,256,N) stores.
// ---------------------------------------------------------------------------
__global__ void __launch_bounds__(256) k_out(const int* __restrict__ knn,
                                             const float* __restrict__ gamma,
                                             const float* __restrict__ beta,
                                             float* __restrict__ out) {
    __shared__ float s_a[256], s_sh[256];
    __shared__ float s_o1[128 * 33];
    __shared__ float s_o2[128 * 33];

    const int tid = threadIdx.x;
    {   // derive BN affine params (256 threads, one channel each)
        const int ch = tid;
        float s, sq, inv_cnt;
        if (ch < 128) { s = g_acc[ch];       sq = g_acc[128 + ch]; inv_cnt = 1.f / CNT1; }
        else          { s = g_acc[128 + ch]; sq = g_acc[256 + ch]; inv_cnt = 1.f / CNT2; }
        const float mean = s * inv_cnt;
        const float var  = fmaxf(sq * inv_cnt - mean * mean, 0.f);
        const float a    = gamma[ch] * rsqrtf(var + 1e-5f);
        s_a[ch]  = a;
        s_sh[ch] = beta[ch] - a * mean;
    }
    __syncthreads();

    const int b  = blockIdx.x >> 8;
    const int n0 = (blockIdx.x & 255) << 5;
    const int lane = tid & 31, warp = tid >> 5;
    const int h = lane >> 4;
    const int q = lane & 15;
    const int c0 = q << 3;

    float a1[8], sh1[8], a2[8], sh2[8];
#pragma unroll
    for (int j = 0; j < 8; ++j) {
        a1[j]  = s_a[c0 + j];        sh1[j] = s_sh[c0 + j];
        a2[j]  = s_a[128 + c0 + j];  sh2[j] = s_sh[128 + c0 + j];
    }

    const unsigned* ebh = g_edgeH + ((size_t)b << 19);
#pragma unroll
    for (int it = 0; it < 2; ++it) {
        const int i = warp * 4 + (it << 1) + h;  // 0..31 point within tile
        const int p = (b << 13) + n0 + i;
        const int iv = knn[p * 16 + q];

        const float4 l0 = *(const float4*)&g_localT[((size_t)p << 7) + c0];
        const float4 l1 = *(const float4*)&g_localT[((size_t)p << 7) + c0 + 4];
        const float l[8] = {l0.x, l0.y, l0.z, l0.w, l1.x, l1.y, l1.z, l1.w};

        float accf[8];
#pragma unroll
        for (int j = 0; j < 8; ++j) accf[j] = 0.f;

#pragma unroll
        for (int k = 0; k < 16; ++k) {
            const int ik = __shfl_sync(0xffffffffu, iv, (h << 4) + k);
            const uint4 ev = *(const uint4*)&ebh[((size_t)ik << 6) + (q << 2)];
            const float2 e01 = u2f2(ev.x);
            const float2 e23 = u2f2(ev.y);
            const float2 e45 = u2f2(ev.z);
            const float2 e67 = u2f2(ev.w);
            const float e[8] = {e01.x, e01.y, e23.x, e23.y, e45.x, e45.y, e67.x, e67.y};
#pragma unroll
            for (int j = 0; j < 8; ++j)
                accf[j] += fmaxf(a2[j] * (e[j] - l[j]) + sh2[j], 0.f);
        }
#pragma unroll
        for (int j = 0; j < 8; ++j) {
            s_o1[(c0 + j) * 33 + i] = fmaxf(a1[j] * l[j] + sh1[j], 0.f);
            s_o2[(c0 + j) * 33 + i] = accf[j] * (1.f / 16.f);
        }
    }
    __syncthreads();

    float* ob = out + ((size_t)b << 21) + n0;    // b*256*8192
#pragma unroll
    for (int r = 0; r < 16; ++r) {
        const int t  = tid + (r << 8);
        const int c  = t >> 5;
        const int i2 = t & 31;
        ob[(size_t)c * NPTS + i2]         = s_o1[c * 33 + i2];
        ob[(size_t)(c + 128) * NPTS + i2] = s_o2[c * 33 + i2];
    }
}

// ---------------------------------------------------------------------------
extern "C" void kernel_launch(void* const* d_in, const int* in_sizes, int n_in,
                              void* d_out, int out_size) {
    const float* feat  = (const float*)d_in[0];
    const int*   knn   = (const int*)  d_in[1];
    const float* W1    = (const float*)d_in[2];
    const float* W2    = (const float*)d_in[3];
    const float* gamma = (const float*)d_in[4];
    const float* beta  = (const float*)d_in[5];
    float* out = (float*)d_out;

    k_gemm <<<512, 256>>>(feat, W1, W2);
    k_stats<<<512, 256>>>(knn);
    k_out  <<<1024, 256>>>(knn, gamma, beta, out);
}